// round 5
// baseline (speedup 1.0000x reference)
#include <cuda_runtime.h>
#include <cuda_bf16.h>
#include <cstdint>

#define K_DIM 512
#define O_DIM 8
#define JX    4096           // K_DIM * O_DIM
#define SZ    (K_DIM * K_DIM * O_DIM)

// ---------------- scratch (no allocations allowed) ----------------
__device__ __nv_bfloat16 g_Abf[(size_t)JX * K_DIM];   // A'[(j,x)][k] * Pb[j]*Pc[k]
__device__ __nv_bfloat16 g_Bbf[(size_t)JX * K_DIM];   // B'[(i,y)][k] * Pa[i]
__device__ float g_partial[1024 * 512];               // per-CTA probs partials
__device__ float g_partial2[16 * 512];                // stage-2 partials

__device__ __forceinline__ uint32_t smem_u32(const void* p) {
    return (uint32_t)__cvta_generic_to_shared(p);
}

// ---------------- conversion: A[j,k,x]*Pb[j]*Pc[k] -> Abf[(j*8+x)][k] (bf16) ---
__global__ void convA_kernel(const float* __restrict__ y) {
    const float* Pb = y + 512;
    const float* Pc = y + 1024;
    const float* A  = y + 1536;
    __shared__ float sA[K_DIM * 9];
    int j = blockIdx.x;
    float pb = Pb[j];
    const float* Aj = A + (size_t)j * (K_DIM * O_DIM);
    for (int t = threadIdx.x; t < K_DIM * O_DIM; t += blockDim.x) {
        int k = t >> 3, x = t & 7;
        sA[k * 9 + x] = Aj[t];                 // coalesced read
    }
    __syncthreads();
    for (int t = threadIdx.x; t < K_DIM * O_DIM; t += blockDim.x) {
        int x = t >> 9, k = t & 511;
        float v = sA[k * 9 + x] * pb * Pc[k];
        g_Abf[(size_t)(j * 8 + x) * K_DIM + k] = __float2bfloat16_rn(v);  // coalesced write
    }
}

// ---------------- conversion: B[k][iy]*Pa[iy>>3] -> Bbf[iy][k] (bf16 transpose) --
__global__ void convB_kernel(const float* __restrict__ y) {
    const float* Pa = y;
    const float* B  = y + 1536 + SZ;
    __shared__ float tile[32][33];
    int iy0 = blockIdx.x * 32;   // over 4096
    int k0  = blockIdx.y * 32;   // over 512
    int c = threadIdx.x & 31;
    int r0 = threadIdx.x >> 5;   // 0..7
#pragma unroll
    for (int s = 0; s < 4; s++) {
        int r = r0 + s * 8;
        tile[r][c] = B[(size_t)(k0 + r) * JX + iy0 + c];
    }
    __syncthreads();
#pragma unroll
    for (int s = 0; s < 4; s++) {
        int r = r0 + s * 8;
        int iy = iy0 + r;
        float v = tile[c][r] * Pa[iy >> 3];
        g_Bbf[(size_t)iy * K_DIM + k0 + c] = __float2bfloat16_rn(v);
    }
}

// ---------------- GEMM (bf16 mma.sync) + fused C-contraction epilogue ----------
// D[jx, iy] = sum_k Abf[jx,k]*Bbf[iy,k]; probs[x,y,z] += D * C[i,j,z]
__global__ void __launch_bounds__(256) gemm_kernel(const float* __restrict__ y) {
    const float* C = y + 1536 + 2 * (size_t)SZ;

    __shared__ __align__(16) unsigned char smem[36864];
    __nv_bfloat16* As = (__nv_bfloat16*)smem;          // [128][72]
    __nv_bfloat16* Bs = As + 128 * 72;                 // [128][72]
    float* Cs    = (float*)smem;                       // epilogue: [16][16][8] = 8KB
    float* warpP = Cs + 2048;                          // epilogue: [8][512]   = 16KB

    const int tid  = threadIdx.x;
    const int lane = tid & 31, wid = tid >> 5;
    const int wm = wid & 3;       // 4 row-groups of 32
    const int wn = wid >> 2;      // 2 col-groups of 64
    const int bm = blockIdx.x, bn = blockIdx.y;

    float acc[2][8][4];
#pragma unroll
    for (int a = 0; a < 2; a++)
#pragma unroll
        for (int b = 0; b < 8; b++)
#pragma unroll
            for (int c = 0; c < 4; c++) acc[a][b][c] = 0.f;

    for (int kt = 0; kt < K_DIM; kt += 64) {
        // load 128x64 bf16 tiles of A and B (row stride 72 to dodge bank conflicts)
#pragma unroll
        for (int s = 0; s < 4; s++) {
            int q = tid + s * 256;
            int row = q >> 3, c16 = q & 7;
            const uint4* srcA = (const uint4*)g_Abf +
                ((size_t)(bm * 128 + row) * (K_DIM / 8) + (kt >> 3) + c16);
            *(uint4*)(As + row * 72 + c16 * 8) = *srcA;
            const uint4* srcB = (const uint4*)g_Bbf +
                ((size_t)(bn * 128 + row) * (K_DIM / 8) + (kt >> 3) + c16);
            *(uint4*)(Bs + row * 72 + c16 * 8) = *srcB;
        }
        __syncthreads();

#pragma unroll
        for (int ks = 0; ks < 64; ks += 16) {
            uint32_t a[2][4];
#pragma unroll
            for (int mt = 0; mt < 2; mt++) {
                uint32_t addr = smem_u32(As + (wm * 32 + mt * 16 + (lane & 15)) * 72
                                            + ks + (lane >> 4) * 8);
                asm volatile("ldmatrix.sync.aligned.m8n8.x4.shared.b16 {%0,%1,%2,%3}, [%4];"
                             : "=r"(a[mt][0]), "=r"(a[mt][1]), "=r"(a[mt][2]), "=r"(a[mt][3])
                             : "r"(addr));
            }
            // B stored [n][k] K-contiguous == B col-major: NON-trans ldmatrix gives
            // exactly the m16n8k16 col-major B fragment.
            uint32_t b[4][4];
#pragma unroll
            for (int p = 0; p < 4; p++) {
                uint32_t addr = smem_u32(Bs + (wn * 64 + p * 16 + ((lane >> 3) & 1) * 8 + (lane & 7)) * 72
                                            + ks + (lane >> 4) * 8);
                asm volatile("ldmatrix.sync.aligned.m8n8.x4.shared.b16 {%0,%1,%2,%3}, [%4];"
                             : "=r"(b[p][0]), "=r"(b[p][1]), "=r"(b[p][2]), "=r"(b[p][3])
                             : "r"(addr));
            }
#pragma unroll
            for (int mt = 0; mt < 2; mt++)
#pragma unroll
                for (int nt = 0; nt < 8; nt++) {
                    const int p = nt >> 1, h = nt & 1;
                    asm volatile(
                        "mma.sync.aligned.m16n8k16.row.col.f32.bf16.bf16.f32 "
                        "{%0,%1,%2,%3}, {%4,%5,%6,%7}, {%8,%9}, {%0,%1,%2,%3};"
                        : "+f"(acc[mt][nt][0]), "+f"(acc[mt][nt][1]),
                          "+f"(acc[mt][nt][2]), "+f"(acc[mt][nt][3])
                        : "r"(a[mt][0]), "r"(a[mt][1]), "r"(a[mt][2]), "r"(a[mt][3]),
                          "r"(b[p][h]), "r"(b[p][2 + h]));
                }
        }
        __syncthreads();
    }

    // ---- epilogue: load the 16x16 (i,j) block of C (8 z each) into smem -------
    {
        int il = tid >> 4, jl = tid & 15;
        const float4* src = (const float4*)(C + ((size_t)(bn * 16 + il) * K_DIM + (bm * 16 + jl)) * 8);
        float4 v0 = src[0], v1 = src[1];
        float4* dst = (float4*)(Cs + (il * 16 + jl) * 8);
        dst[0] = v0; dst[1] = v1;
    }
    __syncthreads();

    // lane owns x = lane>>2 (single x!), y in {2c, 2c+1}, all 8 z -> 16 accumulators
    float pl[2][8];
#pragma unroll
    for (int z = 0; z < 8; z++) { pl[0][z] = 0.f; pl[1][z] = 0.f; }

#pragma unroll
    for (int mt = 0; mt < 2; mt++)
#pragma unroll
        for (int hh = 0; hh < 2; hh++) {
            const int jl = wm * 4 + mt * 2 + hh;
#pragma unroll
            for (int nt = 0; nt < 8; nt++) {
                const int il = wn * 8 + nt;
                const float* crow = Cs + (il * 16 + jl) * 8;   // broadcast across warp
                const float d0 = acc[mt][nt][hh * 2 + 0];
                const float d1 = acc[mt][nt][hh * 2 + 1];
#pragma unroll
                for (int z = 0; z < 8; z++) {
                    float cz = crow[z];
                    pl[0][z] += d0 * cz;
                    pl[1][z] += d1 * cz;
                }
            }
        }

    // per-warp partial probs (each lane writes its unique 16 slots)
    {
        const int x = lane >> 2, yb = (lane & 3) * 2;
        float* wp = warpP + wid * 512 + x * 64 + yb * 8;
#pragma unroll
        for (int z = 0; z < 8; z++) { wp[z] = pl[0][z]; wp[8 + z] = pl[1][z]; }
    }
    __syncthreads();

    // fixed-order cross-warp reduce -> deterministic per-CTA partial
    const int ctaId = bn * gridDim.x + bm;
    for (int e = tid; e < 512; e += 256) {
        float s = 0.f;
#pragma unroll
        for (int w = 0; w < 8; w++) s += warpP[w * 512 + e];
        g_partial[(size_t)ctaId * 512 + e] = s;
    }
}

// ---------------- deterministic reductions ----------------
__global__ void reduce_stage_kernel() {
    int e = threadIdx.x;       // 512
    int b = blockIdx.x;        // 16
    float s = 0.f;
    for (int c = b * 64; c < (b + 1) * 64; c++)
        s += g_partial[(size_t)c * 512 + e];
    g_partial2[b * 512 + e] = s;
}

__global__ void finalize_kernel(const float* __restrict__ y_true, float* __restrict__ out) {
    __shared__ float red[512];
    int e = threadIdx.x;       // 512
    float s = 0.f;
#pragma unroll
    for (int b = 0; b < 16; b++) s += g_partial2[b * 512 + e];
    out[1 + e] = s;                                   // probs
    float p = fminf(fmaxf(s, 1e-10f), 1.0f);          // clip
    float t = y_true[e];
    red[e] = t * (logf(t + 1e-10f) - logf(p));
    __syncthreads();
    for (int st = 256; st > 0; st >>= 1) {
        if (e < st) red[e] += red[e + st];
        __syncthreads();
    }
    if (e == 0) out[0] = red[0];                      // d
}

// ---------------- launch ----------------
extern "C" void kernel_launch(void* const* d_in, const int* in_sizes, int n_in,
                              void* d_out, int out_size) {
    const float* y_pred = (const float*)d_in[0];
    const float* y_true = (const float*)d_in[1];
    float* out = (float*)d_out;

    convA_kernel<<<512, 256>>>(y_pred);
    convB_kernel<<<dim3(128, 16), 256>>>(y_pred);
    gemm_kernel<<<dim3(32, 32), 256>>>(y_pred);
    reduce_stage_kernel<<<16, 512>>>();
    finalize_kernel<<<1, 512>>>(y_true, out);
}